// round 14
// baseline (speedup 1.0000x reference)
#include <cuda_runtime.h>
#include <cuda_bf16.h>

#define NLEV 16
#define LOG2_T 19
#define TSIZE (1u << LOG2_T)
#define TMASK (TSIZE - 1u)
#define PRIME_Y 2654435761u
#define PRIME_Z 805459861u

#define CAP   2200000
#define NBINS (1 << 18)      // 18-bit Morton key at res 64
#define NCHUNK 256           // NBINS / 1024

typedef unsigned long long ull;

// Static scratch (allocation-free): sorted coords, permutation, histogram.
__device__ float4   g_xs[CAP];
__device__ int      g_perm[CAP];
__device__ unsigned g_hist[NBINS];
__device__ unsigned g_bsum[NCHUNK];

// ---------------- sorting pre-pass (R11 winner, unchanged) ----------------

__device__ __forceinline__ unsigned morton_key(float x0, float x1, float x2) {
    int cx = (int)(x0 * 64.0f); cx = cx < 0 ? 0 : (cx > 63 ? 63 : cx);
    int cy = (int)(x1 * 64.0f); cy = cy < 0 ? 0 : (cy > 63 ? 63 : cy);
    int cz = (int)(x2 * 64.0f); cz = cz < 0 ? 0 : (cz > 63 ? 63 : cz);
    unsigned m = 0;
    #pragma unroll
    for (int d = 0; d < 6; d++) {
        m |= ((unsigned)(cx >> d) & 1u) << (3 * d + 0);
        m |= ((unsigned)(cy >> d) & 1u) << (3 * d + 1);
        m |= ((unsigned)(cz >> d) & 1u) << (3 * d + 2);
    }
    return m;
}

__global__ void zero_hist_k() {
    int i = blockIdx.x * blockDim.x + threadIdx.x;
    if (i < NBINS) g_hist[i] = 0u;
}

__global__ void hist_k(const float* __restrict__ x, int N) {
    int i = blockIdx.x * blockDim.x + threadIdx.x;
    if (i >= N) return;
    float x0 = x[3 * i + 0] * 0.5f + 0.5f;
    float x1 = x[3 * i + 1] * 0.5f + 0.5f;
    float x2 = x[3 * i + 2] * 0.5f + 0.5f;
    atomicAdd(&g_hist[morton_key(x0, x1, x2)], 1u);
}

__global__ void scan1_k() {
    __shared__ unsigned sm[1024];
    const int t = threadIdx.x;
    const int g = blockIdx.x * 1024 + t;
    const unsigned v = g_hist[g];
    sm[t] = v;
    __syncthreads();
    for (int off = 1; off < 1024; off <<= 1) {
        unsigned u = (t >= off) ? sm[t - off] : 0u;
        __syncthreads();
        sm[t] += u;
        __syncthreads();
    }
    g_hist[g] = sm[t] - v;
    if (t == 1023) g_bsum[blockIdx.x] = sm[t];
}

__global__ void scan2_k() {
    __shared__ unsigned sm[NCHUNK];
    const int t = threadIdx.x;
    const unsigned v = g_bsum[t];
    sm[t] = v;
    __syncthreads();
    for (int off = 1; off < NCHUNK; off <<= 1) {
        unsigned u = (t >= off) ? sm[t - off] : 0u;
        __syncthreads();
        sm[t] += u;
        __syncthreads();
    }
    g_bsum[t] = sm[t] - v;
}

__global__ void add_k() {
    const int g = blockIdx.x * 1024 + threadIdx.x;
    g_hist[g] += g_bsum[blockIdx.x];
}

__global__ void scatter_k(const float* __restrict__ x, int N) {
    int i = blockIdx.x * blockDim.x + threadIdx.x;
    if (i >= N) return;
    float x0 = x[3 * i + 0] * 0.5f + 0.5f;
    float x1 = x[3 * i + 1] * 0.5f + 0.5f;
    float x2 = x[3 * i + 2] * 0.5f + 0.5f;
    unsigned key = morton_key(x0, x1, x2);
    unsigned slot = atomicAdd(&g_hist[key], 1u);
    g_xs[slot] = make_float4(x0, x1, x2, 0.0f);
    g_perm[slot] = i;
}

// ---------------- main fused kernel ----------------

__device__ __forceinline__ ull fma2u(ull a, ull b, ull c) {
    ull d;
    asm("fma.rn.f32x2 %0, %1, %2, %3;" : "=l"(d) : "l"(a), "l"(b), "l"(c));
    return d;
}
__device__ __forceinline__ ull pack2(float lo, float hi) {
    ull r;
    asm("mov.b64 %0, {%1, %2};" : "=l"(r) : "f"(lo), "f"(hi));
    return r;
}
__device__ __forceinline__ void unpack2(ull v, float& lo, float& hi) {
    asm("mov.b64 {%0, %1}, %2;" : "=f"(lo), "=f"(hi) : "l"(v));
}

// pack value as (bf16 hi << 16) | bf16(residual): unpack to two tf32-valid
// operands with one AND + one SHL (no cvt on the hot path).
__device__ __forceinline__ unsigned pksplit(float v) {
    __nv_bfloat16 h = __float2bfloat16(v);
    float hf = __bfloat162float(h);
    __nv_bfloat16 l = __float2bfloat16(v - hf);
    return ((unsigned)__bfloat16_as_ushort(h) << 16) |
           (unsigned)__bfloat16_as_ushort(l);
}

// m16n8k4 tf32 mma: A = {(g,t),(g+8,t)}, B = {(t,g)}, C row g/g+8 x col 2t/2t+1
__device__ __forceinline__ void mma4(float& c0, float& c1, float& c2, float& c3,
                                     unsigned a0, unsigned a1, unsigned b0) {
    asm("mma.sync.aligned.m16n8k4.row.col.f32.tf32.tf32.f32 "
        "{%0,%1,%2,%3}, {%4,%5}, {%6}, {%0,%1,%2,%3};"
        : "+f"(c0), "+f"(c1), "+f"(c2), "+f"(c3)
        : "r"(a0), "r"(a1), "r"(b0));
}

// dynamic smem layout (4B units)
#define SM_W1   0            // 2048 floats
#define SM_B1   2048         // 64
#define SM_B2   2112         // 64
#define SM_W3   2176         // 64
#define SM_RES  2240         // 16
#define SM_B3   2256         // 1
#define SM_W2P  2272         // 64 x 72 u32 (packed bf16 hi/lo), pad->bank 8t+g
#define SM_A    6880         // 8 warps x 32 x 68 u32 (packed), pad->bank 4g+t
#define SM_TOT  (SM_A + 8 * 32 * 68)       // 24288 u32 = 97152 B

__global__ __launch_bounds__(256, 2)
void hashgrid_mlp_kernel(const float2* __restrict__ tables,
                         const float*  __restrict__ resolutions,
                         const float*  __restrict__ W1, const float* __restrict__ b1,
                         const float*  __restrict__ W2, const float* __restrict__ b2,
                         const float*  __restrict__ W3, const float* __restrict__ b3,
                         float* __restrict__ out, int N)
{
    extern __shared__ __align__(16) float smem[];
    float*    sW1  = smem + SM_W1;
    float*    sB1  = smem + SM_B1;
    float*    sB2  = smem + SM_B2;
    float*    sW3  = smem + SM_W3;
    float*    sRes = smem + SM_RES;
    unsigned* sW2p = (unsigned*)(smem + SM_W2P);
    unsigned* sA   = (unsigned*)(smem + SM_A);

    const int tid = threadIdx.x;
    for (int k = tid; k < 2048; k += 256) sW1[k] = W1[k];
    for (int k = tid; k < 4096; k += 256) {
        int r = k >> 6, n = k & 63;
        sW2p[r * 72 + n] = pksplit(W2[k]);
    }
    if (tid < 64) { sB1[tid] = b1[tid]; sB2[tid] = b2[tid]; sW3[tid] = W3[tid]; }
    if (tid < 16) sRes[tid] = resolutions[tid];
    if (tid == 0) smem[SM_B3] = b3[0];
    __syncthreads();

    const int gi = blockIdx.x * 256 + tid;
    const int i = gi < N ? gi : (N - 1);     // clamp: full warps for mma

    const float4 xs = g_xs[i];               // sorted, mapped to [0,1]
    const float x0 = xs.x, x1 = xs.y, x2 = xs.z;

    // ---- encode + layer 1 (R5/R11 winning structure, unchanged) ----
    ull h1u[32];
    #pragma unroll
    for (int j = 0; j < 32; j++) h1u[j] = ((const ull*)sB1)[j];

    float2   tbuf[2][8];
    float    wbuf[2][3];
    unsigned mbuf[2];

    auto issue = [&](int L, float2* tb, float* wb, unsigned& mb) {
        const float res = sRes[L];
        const float px = x0 * res, py = x1 * res, pz = x2 * res;
        const float fx = floorf(px), fy = floorf(py), fz = floorf(pz);
        wb[0] = px - fx; wb[1] = py - fy; wb[2] = pz - fz;
        const unsigned cx = (unsigned)fx, cy = (unsigned)fy, cz = (unsigned)fz;
        const unsigned hy0 = cy * PRIME_Y, hy1 = hy0 + PRIME_Y;
        const unsigned hz0 = cz * PRIME_Z, hz1 = hz0 + PRIME_Z;
        unsigned rr[4];
        rr[0] = hy0 ^ hz0; rr[1] = hy1 ^ hz0; rr[2] = hy0 ^ hz1; rr[3] = hy1 ^ hz1;
        const float2* __restrict__ base = tables + (size_t)L * TSIZE;
        unsigned m = 0;
        if (!(cx & 1u)) {
            #pragma unroll
            for (int j = 0; j < 4; j++) {
                const unsigned i0 = (cx ^ rr[j]) & TMASK;
                m |= (i0 & 1u) << j;
                const float4 v = __ldg((const float4*)(base + (i0 & ~1u)));
                tb[2 * j]     = make_float2(v.x, v.y);
                tb[2 * j + 1] = make_float2(v.z, v.w);
            }
        } else {
            #pragma unroll
            for (int j = 0; j < 4; j++) {
                const unsigned i0 = (cx        ^ rr[j]) & TMASK;
                const unsigned i1 = ((cx + 1u) ^ rr[j]) & TMASK;
                tb[2 * j]     = __ldg(base + i0);
                tb[2 * j + 1] = __ldg(base + i1);
            }
        }
        mb = m;
    };

    issue(0, tbuf[0], wbuf[0], mbuf[0]);

    #pragma unroll
    for (int L = 0; L < NLEV; L++) {
        const int cur = L & 1;
        if (L < NLEV - 1) issue(L + 1, tbuf[cur ^ 1], wbuf[cur ^ 1], mbuf[cur ^ 1]);

        const float wx1 = wbuf[cur][0], wy1 = wbuf[cur][1], wz1 = wbuf[cur][2];
        const float wx0 = 1.0f - wx1, wy0 = 1.0f - wy1, wz0 = 1.0f - wz1;
        float wyz[4];
        wyz[0] = wy0 * wz0; wyz[1] = wy1 * wz0; wyz[2] = wy0 * wz1; wyz[3] = wy1 * wz1;
        const float2* t = tbuf[cur];
        const unsigned m = mbuf[cur];
        float f0 = 0.0f, f1 = 0.0f;
        #pragma unroll
        for (int j = 0; j < 4; j++) {
            const bool  s  = (m >> j) & 1u;
            const float wl = s ? wx1 : wx0;
            const float wh = s ? wx0 : wx1;
            const float cl = wl * wyz[j], ch = wh * wyz[j];
            f0 += cl * t[2 * j].x + ch * t[2 * j + 1].x;
            f1 += cl * t[2 * j].y + ch * t[2 * j + 1].y;
        }

        const ull a0 = pack2(f0, f0);
        const ull a1 = pack2(f1, f1);
        const ulonglong2* __restrict__ wv =
            (const ulonglong2*)(sW1 + (2 * L) * 64);
        #pragma unroll
        for (int q = 0; q < 16; q++) {
            ulonglong2 Wp = wv[q];
            h1u[2 * q]     = fma2u(a0, Wp.x, h1u[2 * q]);
            h1u[2 * q + 1] = fma2u(a0, Wp.y, h1u[2 * q + 1]);
        }
        #pragma unroll
        for (int q = 0; q < 16; q++) {
            ulonglong2 Wp = wv[16 + q];
            h1u[2 * q]     = fma2u(a1, Wp.x, h1u[2 * q]);
            h1u[2 * q + 1] = fma2u(a1, Wp.y, h1u[2 * q + 1]);
        }
    }

    // ---- stage relu(h1) as packed bf16 hi/lo: row = lane, 64 cols, pad 68 ----
    const int warp = tid >> 5;
    const int lane = tid & 31;
    unsigned* Aw = sA + warp * (32 * 68);
    #pragma unroll
    for (int j = 0; j < 16; j++) {
        float v0, v1, v2, v3;
        unpack2(h1u[2 * j],     v0, v1);
        unpack2(h1u[2 * j + 1], v2, v3);
        uint4 pk;
        pk.x = pksplit(fmaxf(v0, 0.0f));
        pk.y = pksplit(fmaxf(v1, 0.0f));
        pk.z = pksplit(fmaxf(v2, 0.0f));
        pk.w = pksplit(fmaxf(v3, 0.0f));
        *(uint4*)(Aw + lane * 68 + 4 * j) = pk;
    }
    __syncwarp();

    // ---- layer 2 + 3 via tf32 mma (3-term bf16 split) ----
    const int g = lane >> 2, t4 = lane & 3;
    float pr[4] = {0.f, 0.f, 0.f, 0.f};      // [mt*2 + rowhalf] partial h3 dots

    #pragma unroll
    for (int mt = 0; mt < 2; mt++) {
        // preload this mtile's A fragments for all 16 k-tiles
        unsigned ah[16][2], al[16][2];
        #pragma unroll
        for (int kt = 0; kt < 16; kt++) {
            unsigned p0 = Aw[(mt * 16 + g)     * 68 + kt * 4 + t4];
            unsigned p1 = Aw[(mt * 16 + g + 8) * 68 + kt * 4 + t4];
            ah[kt][0] = p0 & 0xFFFF0000u; al[kt][0] = p0 << 16;
            ah[kt][1] = p1 & 0xFFFF0000u; al[kt][1] = p1 << 16;
        }
        #pragma unroll
        for (int nt = 0; nt < 8; nt++) {
            float c0 = sB2[nt * 8 + 2 * t4];
            float c1 = sB2[nt * 8 + 2 * t4 + 1];
            float c2 = c0, c3 = c1;
            #pragma unroll
            for (int kt = 0; kt < 16; kt++) {
                const unsigned bp = sW2p[(kt * 4 + t4) * 72 + nt * 8 + g];
                const unsigned bh = bp & 0xFFFF0000u, bl = bp << 16;
                mma4(c0, c1, c2, c3, ah[kt][0], ah[kt][1], bh);
                mma4(c0, c1, c2, c3, ah[kt][0], ah[kt][1], bl);
                mma4(c0, c1, c2, c3, al[kt][0], al[kt][1], bh);
            }
            const float w0 = sW3[nt * 8 + 2 * t4];
            const float w1 = sW3[nt * 8 + 2 * t4 + 1];
            pr[mt * 2 + 0] += fmaxf(c0, 0.f) * w0 + fmaxf(c1, 0.f) * w1;
            pr[mt * 2 + 1] += fmaxf(c2, 0.f) * w0 + fmaxf(c3, 0.f) * w1;
        }
    }

    // reduce over the 4 lanes sharing a row-group (t4 = 0..3 hold disjoint cols)
    #pragma unroll
    for (int d = 1; d <= 2; d <<= 1) {
        pr[0] += __shfl_xor_sync(0xffffffffu, pr[0], d);
        pr[1] += __shfl_xor_sync(0xffffffffu, pr[1], d);
        pr[2] += __shfl_xor_sync(0xffffffffu, pr[2], d);
        pr[3] += __shfl_xor_sync(0xffffffffu, pr[3], d);
    }

    if (t4 == 0) {
        const int wb = blockIdx.x * 256 + warp * 32;
        const float bias3 = smem[SM_B3];
        int p;
        p = wb + g;          if (p < N) out[g_perm[p]] = pr[0] + bias3;
        p = wb + g + 8;      if (p < N) out[g_perm[p]] = pr[1] + bias3;
        p = wb + 16 + g;     if (p < N) out[g_perm[p]] = pr[2] + bias3;
        p = wb + 24 + g;     if (p < N) out[g_perm[p]] = pr[3] + bias3;
    }
}

extern "C" void kernel_launch(void* const* d_in, const int* in_sizes, int n_in,
                              void* d_out, int out_size)
{
    const float*  x    = (const float*) d_in[0];
    const float2* tabs = (const float2*)d_in[1];
    const float*  res  = (const float*) d_in[2];
    const float*  W1   = (const float*) d_in[3];
    const float*  b1   = (const float*) d_in[4];
    const float*  W2   = (const float*) d_in[5];
    const float*  b2   = (const float*) d_in[6];
    const float*  W3   = (const float*) d_in[7];
    const float*  b3   = (const float*) d_in[8];

    const int N = in_sizes[0] / 3;
    const int threads = 256;
    const int blocks = (N + threads - 1) / threads;

    // spatial binning presort (all graph-capturable kernel launches)
    zero_hist_k<<<(NBINS + 255) / 256, 256>>>();
    hist_k<<<blocks, threads>>>(x, N);
    scan1_k<<<NCHUNK, 1024>>>();
    scan2_k<<<1, NCHUNK>>>();
    add_k<<<NCHUNK, 1024>>>();
    scatter_k<<<blocks, threads>>>(x, N);

    const int smem_bytes = SM_TOT * (int)sizeof(float);   // 97152
    cudaFuncSetAttribute(hashgrid_mlp_kernel,
                         cudaFuncAttributeMaxDynamicSharedMemorySize, smem_bytes);
    hashgrid_mlp_kernel<<<blocks, threads, smem_bytes>>>(tabs, res, W1, b1,
                                                         W2, b2, W3, b3,
                                                         (float*)d_out, N);
}

// round 15
// speedup vs baseline: 1.1840x; 1.1840x over previous
#include <cuda_runtime.h>
#include <cuda_fp16.h>

#define NLEV 16
#define LOG2_T 19
#define TSIZE (1u << LOG2_T)
#define TMASK (TSIZE - 1u)
#define PRIME_Y 2654435761u
#define PRIME_Z 805459861u

#define CAP   2200000
#define CAPF  2200000u       // float2 stride per level in the feature buffer
#define NBINS (1 << 18)      // 18-bit Morton key at res 64
#define NCHUNK 256           // NBINS / 1024

typedef unsigned long long ull;

// Static scratch (allocation-free).
__device__ float4   g_xs[CAP];
__device__ int      g_perm[CAP];
__device__ unsigned g_hist[NBINS];
__device__ unsigned g_bsum[NCHUNK];
__device__ float2   g_feat2[NLEV * CAP];   // ~282 MB feature staging

// ---------------- sorting pre-pass (R11 winner, unchanged) ----------------

__device__ __forceinline__ unsigned morton_key(float x0, float x1, float x2) {
    int cx = (int)(x0 * 64.0f); cx = cx < 0 ? 0 : (cx > 63 ? 63 : cx);
    int cy = (int)(x1 * 64.0f); cy = cy < 0 ? 0 : (cy > 63 ? 63 : cy);
    int cz = (int)(x2 * 64.0f); cz = cz < 0 ? 0 : (cz > 63 ? 63 : cz);
    unsigned m = 0;
    #pragma unroll
    for (int d = 0; d < 6; d++) {
        m |= ((unsigned)(cx >> d) & 1u) << (3 * d + 0);
        m |= ((unsigned)(cy >> d) & 1u) << (3 * d + 1);
        m |= ((unsigned)(cz >> d) & 1u) << (3 * d + 2);
    }
    return m;
}

__global__ void zero_hist_k() {
    int i = blockIdx.x * blockDim.x + threadIdx.x;
    if (i < NBINS) g_hist[i] = 0u;
}

__global__ void hist_k(const float* __restrict__ x, int N) {
    int i = blockIdx.x * blockDim.x + threadIdx.x;
    if (i >= N) return;
    float x0 = x[3 * i + 0] * 0.5f + 0.5f;
    float x1 = x[3 * i + 1] * 0.5f + 0.5f;
    float x2 = x[3 * i + 2] * 0.5f + 0.5f;
    atomicAdd(&g_hist[morton_key(x0, x1, x2)], 1u);
}

__global__ void scan1_k() {
    __shared__ unsigned sm[1024];
    const int t = threadIdx.x;
    const int g = blockIdx.x * 1024 + t;
    const unsigned v = g_hist[g];
    sm[t] = v;
    __syncthreads();
    for (int off = 1; off < 1024; off <<= 1) {
        unsigned u = (t >= off) ? sm[t - off] : 0u;
        __syncthreads();
        sm[t] += u;
        __syncthreads();
    }
    g_hist[g] = sm[t] - v;
    if (t == 1023) g_bsum[blockIdx.x] = sm[t];
}

__global__ void scan2_k() {
    __shared__ unsigned sm[NCHUNK];
    const int t = threadIdx.x;
    const unsigned v = g_bsum[t];
    sm[t] = v;
    __syncthreads();
    for (int off = 1; off < NCHUNK; off <<= 1) {
        unsigned u = (t >= off) ? sm[t - off] : 0u;
        __syncthreads();
        sm[t] += u;
        __syncthreads();
    }
    g_bsum[t] = sm[t] - v;
}

__global__ void add_k() {
    const int g = blockIdx.x * 1024 + threadIdx.x;
    g_hist[g] += g_bsum[blockIdx.x];
}

__global__ void scatter_k(const float* __restrict__ x, int N) {
    int i = blockIdx.x * blockDim.x + threadIdx.x;
    if (i >= N) return;
    float x0 = x[3 * i + 0] * 0.5f + 0.5f;
    float x1 = x[3 * i + 1] * 0.5f + 0.5f;
    float x2 = x[3 * i + 2] * 0.5f + 0.5f;
    unsigned key = morton_key(x0, x1, x2);
    unsigned slot = atomicAdd(&g_hist[key], 1u);
    g_xs[slot] = make_float4(x0, x1, x2, 0.0f);
    g_perm[slot] = i;
}

// ---------------- packed fp32x2 helpers ----------------

__device__ __forceinline__ ull fma2u(ull a, ull b, ull c) {
    ull d;
    asm("fma.rn.f32x2 %0, %1, %2, %3;" : "=l"(d) : "l"(a), "l"(b), "l"(c));
    return d;
}
__device__ __forceinline__ ull pack2(float lo, float hi) {
    ull r;
    asm("mov.b64 %0, {%1, %2};" : "=l"(r) : "f"(lo), "f"(hi));
    return r;
}
__device__ __forceinline__ void unpack2(ull v, float& lo, float& hi) {
    asm("mov.b64 {%0, %1}, %2;" : "=f"(lo), "=f"(hi) : "l"(v));
}

// ---------------- pass 1: hash-grid encode (R11 gather path) ----------------

__global__ __launch_bounds__(256, 2)
void encode_kernel(const float2* __restrict__ tables,
                   const float*  __restrict__ resolutions, int N)
{
    __shared__ float sRes[16];
    const int tid = threadIdx.x;
    if (tid < 16) sRes[tid] = resolutions[tid];
    __syncthreads();

    const unsigned i = blockIdx.x * 256 + tid;
    if (i >= (unsigned)N) return;

    const float4 xs = g_xs[i];           // sorted, mapped to [0,1]
    const float x0 = xs.x, x1 = xs.y, x2 = xs.z;

    float2   tbuf[2][8];
    float    wbuf[2][3];
    unsigned mbuf[2];

    auto issue = [&](int L, float2* tb, float* wb, unsigned& mb) {
        const float res = sRes[L];
        const float px = x0 * res, py = x1 * res, pz = x2 * res;
        const float fx = floorf(px), fy = floorf(py), fz = floorf(pz);
        wb[0] = px - fx; wb[1] = py - fy; wb[2] = pz - fz;
        const unsigned cx = (unsigned)fx, cy = (unsigned)fy, cz = (unsigned)fz;
        const unsigned hy0 = cy * PRIME_Y, hy1 = hy0 + PRIME_Y;
        const unsigned hz0 = cz * PRIME_Z, hz1 = hz0 + PRIME_Z;
        unsigned rr[4];
        rr[0] = hy0 ^ hz0; rr[1] = hy1 ^ hz0; rr[2] = hy0 ^ hz1; rr[3] = hy1 ^ hz1;
        const float2* __restrict__ base = tables + (size_t)L * TSIZE;
        unsigned m = 0;
        if (!(cx & 1u)) {
            #pragma unroll
            for (int j = 0; j < 4; j++) {
                const unsigned i0 = (cx ^ rr[j]) & TMASK;
                m |= (i0 & 1u) << j;
                const float4 v = __ldg((const float4*)(base + (i0 & ~1u)));
                tb[2 * j]     = make_float2(v.x, v.y);
                tb[2 * j + 1] = make_float2(v.z, v.w);
            }
        } else {
            #pragma unroll
            for (int j = 0; j < 4; j++) {
                const unsigned i0 = (cx        ^ rr[j]) & TMASK;
                const unsigned i1 = ((cx + 1u) ^ rr[j]) & TMASK;
                tb[2 * j]     = __ldg(base + i0);
                tb[2 * j + 1] = __ldg(base + i1);
            }
        }
        mb = m;
    };

    issue(0, tbuf[0], wbuf[0], mbuf[0]);

    #pragma unroll
    for (int L = 0; L < NLEV; L++) {
        const int cur = L & 1;
        if (L < NLEV - 1) issue(L + 1, tbuf[cur ^ 1], wbuf[cur ^ 1], mbuf[cur ^ 1]);

        const float wx1 = wbuf[cur][0], wy1 = wbuf[cur][1], wz1 = wbuf[cur][2];
        const float wx0 = 1.0f - wx1, wy0 = 1.0f - wy1, wz0 = 1.0f - wz1;
        float wyz[4];
        wyz[0] = wy0 * wz0; wyz[1] = wy1 * wz0; wyz[2] = wy0 * wz1; wyz[3] = wy1 * wz1;
        const float2* t = tbuf[cur];
        const unsigned m = mbuf[cur];
        float f0 = 0.0f, f1 = 0.0f;
        #pragma unroll
        for (int j = 0; j < 4; j++) {
            const bool  s  = (m >> j) & 1u;
            const float wl = s ? wx1 : wx0;
            const float wh = s ? wx0 : wx1;
            const float cl = wl * wyz[j], ch = wh * wyz[j];
            f0 += cl * t[2 * j].x + ch * t[2 * j + 1].x;
            f1 += cl * t[2 * j].y + ch * t[2 * j + 1].y;
        }
        g_feat2[(unsigned)(L * CAPF) + i] = make_float2(f0, f1);  // coalesced
    }
}

// ---------------- pass 2: MLP, 2 points per thread ----------------

__global__ __launch_bounds__(128, 3)
void mlp_kernel(const float* __restrict__ W1, const float* __restrict__ b1,
                const float* __restrict__ W2, const float* __restrict__ b2,
                const float* __restrict__ W3, const float* __restrict__ b3,
                float* __restrict__ out, int N)
{
    __shared__ __align__(16) float sW1[32 * 64];
    __shared__ __align__(16) float sW2[64 * 64];
    __shared__ __align__(16) float sB1[64];
    __shared__ __align__(16) float sB2[64];
    __shared__ __align__(16) float sW3[64];
    __shared__ float sB3;

    const int tid = threadIdx.x;
    for (int k = tid; k < 32 * 64; k += 128) sW1[k] = W1[k];
    for (int k = tid; k < 64 * 64; k += 128) sW2[k] = W2[k];
    if (tid < 64) { sB1[tid] = b1[tid]; sB2[tid] = b2[tid]; sW3[tid] = W3[tid]; }
    if (tid == 0) sB3 = b3[0];
    __syncthreads();

    const int base = blockIdx.x * 256;
    const int gA = base + tid, gB = base + 128 + tid;
    const unsigned iA = (unsigned)(gA < N ? gA : N - 1);
    const unsigned iB = (unsigned)(gB < N ? gB : N - 1);

    // ---- layer 1: 2 tiles of 32 neurons; weights loaded once per pair ----
    __half2 h1A[32], h1B[32];            // h1[k>>1] holds neurons (k, k|1)
    #pragma unroll
    for (int t = 0; t < 2; t++) {
        ull aA[16], aB[16];
        #pragma unroll
        for (int m = 0; m < 16; m++) {
            const ull bb = ((const ull*)(sB1 + t * 32))[m];
            aA[m] = bb; aB[m] = bb;
        }
        #pragma unroll
        for (int L = 0; L < NLEV; L++) {
            const float2 fA = g_feat2[(unsigned)(L * CAPF) + iA];  // coalesced
            const float2 fB = g_feat2[(unsigned)(L * CAPF) + iB];
            const ull a0A = pack2(fA.x, fA.x), a1A = pack2(fA.y, fA.y);
            const ull a0B = pack2(fB.x, fB.x), a1B = pack2(fB.y, fB.y);
            const ulonglong2* w0 = (const ulonglong2*)(sW1 + (2 * L) * 64 + t * 32);
            const ulonglong2* w1 = (const ulonglong2*)(sW1 + (2 * L + 1) * 64 + t * 32);
            #pragma unroll
            for (int j = 0; j < 8; j++) {
                const ulonglong2 Wa = w0[j];           // LDS.128 broadcast
                aA[2 * j]     = fma2u(a0A, Wa.x, aA[2 * j]);
                aA[2 * j + 1] = fma2u(a0A, Wa.y, aA[2 * j + 1]);
                aB[2 * j]     = fma2u(a0B, Wa.x, aB[2 * j]);
                aB[2 * j + 1] = fma2u(a0B, Wa.y, aB[2 * j + 1]);
            }
            #pragma unroll
            for (int j = 0; j < 8; j++) {
                const ulonglong2 Wb = w1[j];
                aA[2 * j]     = fma2u(a1A, Wb.x, aA[2 * j]);
                aA[2 * j + 1] = fma2u(a1A, Wb.y, aA[2 * j + 1]);
                aB[2 * j]     = fma2u(a1B, Wb.x, aB[2 * j]);
                aB[2 * j + 1] = fma2u(a1B, Wb.y, aB[2 * j + 1]);
            }
        }
        // relu -> fp16 storage (values in [0, ~1e-3]; fp16 rel err ~5e-4)
        #pragma unroll
        for (int m = 0; m < 16; m++) {
            float e0, e1;
            unpack2(aA[m], e0, e1);
            h1A[t * 16 + m] = __floats2half2_rn(fmaxf(e0, 0.f), fmaxf(e1, 0.f));
            unpack2(aB[m], e0, e1);
            h1B[t * 16 + m] = __floats2half2_rn(fmaxf(e0, 0.f), fmaxf(e1, 0.f));
        }
    }

    // ---- layer 2 + 3: 2 tiles; weights loaded once per pair ----
    float outA = sB3, outB = sB3;
    #pragma unroll
    for (int t = 0; t < 2; t++) {
        ull aA[16], aB[16];
        #pragma unroll
        for (int m = 0; m < 16; m++) {
            const ull bb = ((const ull*)(sB2 + t * 32))[m];
            aA[m] = bb; aB[m] = bb;
        }
        #pragma unroll
        for (int k = 0; k < 64; k++) {
            const __half2 hA = h1A[k >> 1], hB = h1B[k >> 1];
            const float vA = (k & 1) ? __high2float(hA) : __low2float(hA);
            const float vB = (k & 1) ? __high2float(hB) : __low2float(hB);
            const ull rA = pack2(vA, vA), rB = pack2(vB, vB);
            const ulonglong2* w = (const ulonglong2*)(sW2 + k * 64 + t * 32);
            #pragma unroll
            for (int j = 0; j < 8; j++) {
                const ulonglong2 Wp = w[j];            // LDS.128 broadcast
                aA[2 * j]     = fma2u(rA, Wp.x, aA[2 * j]);
                aA[2 * j + 1] = fma2u(rA, Wp.y, aA[2 * j + 1]);
                aB[2 * j]     = fma2u(rB, Wp.x, aB[2 * j]);
                aB[2 * j + 1] = fma2u(rB, Wp.y, aB[2 * j + 1]);
            }
        }
        #pragma unroll
        for (int m = 0; m < 16; m++) {
            const float w30 = sW3[t * 32 + 2 * m];
            const float w31 = sW3[t * 32 + 2 * m + 1];
            float e0, e1;
            unpack2(aA[m], e0, e1);
            outA += fmaxf(e0, 0.f) * w30 + fmaxf(e1, 0.f) * w31;
            unpack2(aB[m], e0, e1);
            outB += fmaxf(e0, 0.f) * w30 + fmaxf(e1, 0.f) * w31;
        }
    }

    if (gA < N) out[g_perm[iA]] = outA;
    if (gB < N) out[g_perm[iB]] = outB;
}

extern "C" void kernel_launch(void* const* d_in, const int* in_sizes, int n_in,
                              void* d_out, int out_size)
{
    const float*  x    = (const float*) d_in[0];
    const float2* tabs = (const float2*)d_in[1];
    const float*  res  = (const float*) d_in[2];
    const float*  W1   = (const float*) d_in[3];
    const float*  b1   = (const float*) d_in[4];
    const float*  W2   = (const float*) d_in[5];
    const float*  b2   = (const float*) d_in[6];
    const float*  W3   = (const float*) d_in[7];
    const float*  b3   = (const float*) d_in[8];

    const int N = in_sizes[0] / 3;
    const int threads = 256;
    const int blocks = (N + threads - 1) / threads;

    // spatial binning presort
    zero_hist_k<<<(NBINS + 255) / 256, 256>>>();
    hist_k<<<blocks, threads>>>(x, N);
    scan1_k<<<NCHUNK, 1024>>>();
    scan2_k<<<1, NCHUNK>>>();
    add_k<<<NCHUNK, 1024>>>();
    scatter_k<<<blocks, threads>>>(x, N);

    // pass 1: encode (L1-bound, high occupancy)
    encode_kernel<<<blocks, 256>>>(tabs, res, N);

    // pass 2: MLP (fma-bound, 2 points/thread halves weight-LDS)
    mlp_kernel<<<(N + 255) / 256, 128>>>(W1, b1, W2, b2, W3, b3,
                                         (float*)d_out, N);
}